// round 13
// baseline (speedup 1.0000x reference)
#include <cuda_runtime.h>
#include <cuda_fp16.h>
#include <cstdint>

// ---------------------------------------------------------------------------
// IntentSlotLabellingModel on GB300 (sm_103a), Round 12:
// Zero pre-pass kernels.
//  * L1: fully fused — gathers emb rows (fp32) AND conv_w (fp32) with
//    in-kernel cvt+STS producers, DEPTH=2 register-staged ring. CTAs 0..639
//    additionally transpose w1/w2 -> [N,K] fp16 before their mainloop
//    (ready before L2 by stream order).
//  * L2/L3: byte-identical R9/R11 mainloops (122 / 37 us measured).
//   M=32768, E=512, C=512, H=1024, L=128.
// ---------------------------------------------------------------------------

#define BM 128
#define BN 128
#define BK 64
#define DEPTH 3
#define SSTR_H 72                       // padded row stride in halves (144 B)
#define A_STH (BM * SSTR_H)             // 9216 halves / stage
#define B_STH (BN * SSTR_H)             // 9216 halves / stage
#define STG_H (A_STH + B_STH)           // 18432 halves / stage
#define SMEM_BYTES (DEPTH * STG_H * 2)  // 110592 B (L2/L3, occ 2)
#define L1_SMEM (2 * STG_H * 2)         // 73728 B (L1, DEPTH=2, occ 1)

__device__ __half g_H[32768L * 512];    // post-conv relu (fp16)
__device__ __half g_Z[32768L * 1024];   // post-dec1 relu (fp16)
__device__ __half g_w1t[1024L * 512];   // dec_w1 -> fp16 [N,K]
__device__ __half g_w2t[128L * 1024];   // dec_w2 -> fp16 [N,K]

__device__ __forceinline__ uint32_t smem_u32(const void* p) {
    uint32_t a;
    asm("{ .reg .u64 t; cvta.to.shared.u64 t, %1; cvt.u32.u64 %0, t; }"
        : "=r"(a) : "l"(p));
    return a;
}
__device__ __forceinline__ void cp_async16(uint32_t dst, const void* src) {
    asm volatile("cp.async.cg.shared.global [%0], [%1], 16;"
                 :: "r"(dst), "l"(src) : "memory");
}
__device__ __forceinline__ void cp_commit() {
    asm volatile("cp.async.commit_group;" ::: "memory");
}
template <int N> __device__ __forceinline__ void cp_wait() {
    asm volatile("cp.async.wait_group %0;" :: "n"(N) : "memory");
}
__device__ __forceinline__ void mma_f16(float* d, const uint32_t* a, const uint32_t* b) {
    asm volatile(
        "mma.sync.aligned.m16n8k16.row.col.f32.f16.f16.f32 "
        "{%0,%1,%2,%3}, {%4,%5,%6,%7}, {%8,%9}, {%0,%1,%2,%3};"
        : "+f"(d[0]), "+f"(d[1]), "+f"(d[2]), "+f"(d[3])
        : "r"(a[0]), "r"(a[1]), "r"(a[2]), "r"(a[3]), "r"(b[0]), "r"(b[1]));
}

// 32x32 transpose tile with fp16 cvt: in [K,N] -> out [N,K]
__device__ __forceinline__ void tile_transpose_cvt(
    const float* __restrict__ in, __half* __restrict__ out,
    int K, int N, int bx, int by, int tid)
{
    __shared__ float t[32][33];
    int n0 = bx * 32, k0 = by * 32;
    int x = tid & 31, y = tid >> 5;
    #pragma unroll
    for (int i = 0; i < 32; i += 8)
        t[y + i][x] = in[(long)(k0 + y + i) * N + n0 + x];
    __syncthreads();
    #pragma unroll
    for (int i = 0; i < 32; i += 8)
        out[(long)(n0 + y + i) * K + k0 + x] = __float2half_rn(t[x][y + i]);
    __syncthreads();
}

// ---------------------------------------------------------------------------
// L1 fused kernel: H[128x128 tile] = relu(gather(emb, tok) @ conv_w^T + bias)
// A: fp32 emb rows via tokens; B: fp32 conv_w rows — both LDG+cvt+STS,
// DEPTH=2 ring, 1-stage-ahead register prefetch. 8 warps, warp tile 64x32.
// CTAs 0..639 also transpose w1/w2 (for L2/L3) before their mainloop.
// ---------------------------------------------------------------------------
__global__ void __launch_bounds__(256, 1)
mma_gemm_l1(const float* __restrict__ emb, const int* __restrict__ tokens,
            const float* __restrict__ convw, const float* __restrict__ bias,
            __half* __restrict__ C,
            const float* __restrict__ w1, __half* __restrict__ w1t,
            const float* __restrict__ w2, __half* __restrict__ w2t)
{
    extern __shared__ __half smem[];

    const int tid  = threadIdx.x;
    const int lane = tid & 31;
    const int warp = tid >> 5;
    const int warp_m = (warp >> 2) * 64;     // 0,64
    const int warp_n = (warp & 3) * 32;      // 0,32,64,96
    const int gr = lane >> 2;
    const int gc = lane & 3;

    const int  n0 = blockIdx.x * BN;
    const long m0 = (long)blockIdx.y * BM;
    const int  N = 512, K = 512;

    // ---- distributed weight prep (done once across the grid, uniform branch)
    {
        int bid = blockIdx.y * gridDim.x + blockIdx.x;   // 0..1023
        if (bid < 512) {
            tile_transpose_cvt(w1, w1t, 512, 1024, bid & 31, bid >> 5, tid);
        } else if (bid < 640) {
            int bb = bid - 512;
            tile_transpose_cvt(w2, w2t, 1024, 128, bb & 3, bb >> 2, tid);
        }
    }

    // ---- producers: A (gathered emb) and B (conv_w), 8 float4 each ----
    const int r_base = tid >> 4;             // 0..15
    const int c4     = (tid & 15) * 4;       // float col 0..60
    const float* a_src[8];
    #pragma unroll
    for (int i = 0; i < 8; i++)
        a_src[i] = emb + (long)tokens[m0 + r_base + i * 16] * 512 + c4;
    const float* b_src0 = convw + (long)(n0 + r_base) * K + c4;
    const int soff0 = r_base * SSTR_H + c4;  // halves within tile

    const int S = K / BK;                    // 8

    float4 ra[8], rb[8];
    auto loadAB = [&](int s) {
        const int k0 = s * BK;
        #pragma unroll
        for (int i = 0; i < 8; i++)
            ra[i] = *reinterpret_cast<const float4*>(a_src[i] + k0);
        #pragma unroll
        for (int i = 0; i < 8; i++)
            rb[i] = *reinterpret_cast<const float4*>(b_src0 + k0 + i * 16L * K);
    };
    auto stsAB = [&](int s) {
        __half* As = smem + (s & 1) * STG_H;
        __half* Bs = As + A_STH;
        #pragma unroll
        for (int i = 0; i < 8; i++) {
            __half2 h0 = __floats2half2_rn(ra[i].x, ra[i].y);
            __half2 h1 = __floats2half2_rn(ra[i].z, ra[i].w);
            uint2 u;
            u.x = *reinterpret_cast<uint32_t*>(&h0);
            u.y = *reinterpret_cast<uint32_t*>(&h1);
            *reinterpret_cast<uint2*>(&As[soff0 + i * 16 * SSTR_H]) = u;
        }
        #pragma unroll
        for (int i = 0; i < 8; i++) {
            __half2 h0 = __floats2half2_rn(rb[i].x, rb[i].y);
            __half2 h1 = __floats2half2_rn(rb[i].z, rb[i].w);
            uint2 u;
            u.x = *reinterpret_cast<uint32_t*>(&h0);
            u.y = *reinterpret_cast<uint32_t*>(&h1);
            *reinterpret_cast<uint2*>(&Bs[soff0 + i * 16 * SSTR_H]) = u;
        }
    };

    float acc[4][4][4];
    #pragma unroll
    for (int mt = 0; mt < 4; mt++)
        #pragma unroll
        for (int nt = 0; nt < 4; nt++)
            #pragma unroll
            for (int r = 0; r < 4; r++)
                acc[mt][nt][r] = 0.0f;

    loadAB(0);
    stsAB(0);
    __syncthreads();

    for (int s = 0; s < S; s++) {
        if (s + 1 < S) loadAB(s + 1);        // LDG early, hidden by compute

        const __half* As = smem + (s & 1) * STG_H;
        const __half* Bs = As + A_STH;

        #pragma unroll
        for (int ks = 0; ks < BK; ks += 16) {
            uint32_t af[4][4], bf[4][2];
            #pragma unroll
            for (int mt = 0; mt < 4; mt++) {
                int r = (warp_m + mt * 16 + gr) * SSTR_H + ks + gc * 2;
                af[mt][0] = *reinterpret_cast<const uint32_t*>(&As[r]);
                af[mt][1] = *reinterpret_cast<const uint32_t*>(&As[r + 8 * SSTR_H]);
                af[mt][2] = *reinterpret_cast<const uint32_t*>(&As[r + 8]);
                af[mt][3] = *reinterpret_cast<const uint32_t*>(&As[r + 8 * SSTR_H + 8]);
            }
            #pragma unroll
            for (int nt = 0; nt < 4; nt++) {
                int r = (warp_n + nt * 8 + gr) * SSTR_H + ks + gc * 2;
                bf[nt][0] = *reinterpret_cast<const uint32_t*>(&Bs[r]);
                bf[nt][1] = *reinterpret_cast<const uint32_t*>(&Bs[r + 8]);
            }
            #pragma unroll
            for (int mt = 0; mt < 4; mt++)
                #pragma unroll
                for (int nt = 0; nt < 4; nt++)
                    mma_f16(acc[mt][nt], af[mt], bf[nt]);
        }

        if (s + 1 < S) {
            stsAB(s + 1);                    // other buffer, no race
            __syncthreads();
        }
    }

    // ---- epilogue: bias + relu, half2 stores ----
    #pragma unroll
    for (int nt = 0; nt < 4; nt++) {
        int n = n0 + warp_n + nt * 8 + gc * 2;
        float bb0 = bias[n], bb1 = bias[n + 1];
        #pragma unroll
        for (int mt = 0; mt < 4; mt++) {
            long m = m0 + warp_m + mt * 16 + gr;
            __half2 h0 = __floats2half2_rn(fmaxf(acc[mt][nt][0] + bb0, 0.0f),
                                           fmaxf(acc[mt][nt][1] + bb1, 0.0f));
            __half2 h1 = __floats2half2_rn(fmaxf(acc[mt][nt][2] + bb0, 0.0f),
                                           fmaxf(acc[mt][nt][3] + bb1, 0.0f));
            *reinterpret_cast<__half2*>(C + m * (long)N + n)       = h0;
            *reinterpret_cast<__half2*>(C + (m + 8) * (long)N + n) = h1;
        }
    }
}

// ---------------------------------------------------------------------------
// L2/L3 GEMM (R9 proven, byte-identical): C = A @ B^T + bias
// ---------------------------------------------------------------------------
template <bool HALF_OUT>
__global__ void __launch_bounds__(256, 2)
mma_gemm(const __half* __restrict__ A, const __half* __restrict__ B,
         const float* __restrict__ bias, void* __restrict__ Cv,
         int N, int K)
{
    extern __shared__ __half smem[];
    const uint32_t sbase = smem_u32(smem);

    const int tid  = threadIdx.x;
    const int lane = tid & 31;
    const int warp = tid >> 5;
    const int warp_m = (warp >> 2) * 64;
    const int warp_n = (warp & 3) * 32;
    const int gr = lane >> 2;
    const int gc = lane & 3;

    const int  n0 = blockIdx.x * BN;
    const long m0 = (long)blockIdx.y * BM;

    const int r0 = tid >> 3;
    const int c8 = (tid & 7) * 8;
    const __half* a_base = A + (m0 + r0) * (long)K + c8;
    const __half* b_base = B + (long)(n0 + r0) * (long)K + c8;
    const uint32_t a_dst0 = sbase + (uint32_t)(r0 * SSTR_H + c8) * 2u;
    const uint32_t b_dst0 = sbase + (uint32_t)(A_STH + r0 * SSTR_H + c8) * 2u;
    const long  g_step = 32L * K;
    const uint32_t s_step = 32u * SSTR_H * 2u;

    const int S = K / BK;

    auto issue = [&](int s) {
        const uint32_t so = (uint32_t)((s % DEPTH) * STG_H * 2);
        const int k0 = s * BK;
        #pragma unroll
        for (int i = 0; i < 4; i++)
            cp_async16(a_dst0 + so + i * s_step, a_base + k0 + i * g_step);
        #pragma unroll
        for (int i = 0; i < 4; i++)
            cp_async16(b_dst0 + so + i * s_step, b_base + k0 + i * g_step);
    };

    issue(0); cp_commit();
    issue(1); cp_commit();

    float acc[4][4][4];
    #pragma unroll
    for (int mt = 0; mt < 4; mt++)
        #pragma unroll
        for (int nt = 0; nt < 4; nt++)
            #pragma unroll
            for (int r = 0; r < 4; r++)
                acc[mt][nt][r] = 0.0f;

    for (int s = 0; s < S; s++) {
        cp_wait<DEPTH - 2>();
        __syncthreads();
        if (s + 2 < S) issue(s + 2);
        cp_commit();

        const __half* As = smem + (s % DEPTH) * STG_H;
        const __half* Bs = As + A_STH;

        #pragma unroll
        for (int ks = 0; ks < BK; ks += 16) {
            uint32_t af[4][4], bf[4][2];
            #pragma unroll
            for (int mt = 0; mt < 4; mt++) {
                int r = (warp_m + mt * 16 + gr) * SSTR_H + ks + gc * 2;
                af[mt][0] = *reinterpret_cast<const uint32_t*>(&As[r]);
                af[mt][1] = *reinterpret_cast<const uint32_t*>(&As[r + 8 * SSTR_H]);
                af[mt][2] = *reinterpret_cast<const uint32_t*>(&As[r + 8]);
                af[mt][3] = *reinterpret_cast<const uint32_t*>(&As[r + 8 * SSTR_H + 8]);
            }
            #pragma unroll
            for (int nt = 0; nt < 4; nt++) {
                int r = (warp_n + nt * 8 + gr) * SSTR_H + ks + gc * 2;
                bf[nt][0] = *reinterpret_cast<const uint32_t*>(&Bs[r]);
                bf[nt][1] = *reinterpret_cast<const uint32_t*>(&Bs[r + 8]);
            }
            #pragma unroll
            for (int mt = 0; mt < 4; mt++)
                #pragma unroll
                for (int nt = 0; nt < 4; nt++)
                    mma_f16(acc[mt][nt], af[mt], bf[nt]);
        }
    }

    #pragma unroll
    for (int nt = 0; nt < 4; nt++) {
        int n = n0 + warp_n + nt * 8 + gc * 2;
        float bb0 = bias[n], bb1 = bias[n + 1];
        #pragma unroll
        for (int mt = 0; mt < 4; mt++) {
            long m = m0 + warp_m + mt * 16 + gr;
            float x0 = acc[mt][nt][0] + bb0, x1 = acc[mt][nt][1] + bb1;
            float x2 = acc[mt][nt][2] + bb0, x3 = acc[mt][nt][3] + bb1;
            if (HALF_OUT) {
                __half* C = (__half*)Cv;
                __half2 h0 = __floats2half2_rn(fmaxf(x0, 0.0f), fmaxf(x1, 0.0f));
                __half2 h1 = __floats2half2_rn(fmaxf(x2, 0.0f), fmaxf(x3, 0.0f));
                *reinterpret_cast<__half2*>(C + m * (long)N + n)       = h0;
                *reinterpret_cast<__half2*>(C + (m + 8) * (long)N + n) = h1;
            } else {
                float* C = (float*)Cv;
                *reinterpret_cast<float2*>(C + m * (long)N + n)       = make_float2(x0, x1);
                *reinterpret_cast<float2*>(C + (m + 8) * (long)N + n) = make_float2(x2, x3);
            }
        }
    }
}

extern "C" void kernel_launch(void* const* d_in, const int* in_sizes, int n_in,
                              void* d_out, int out_size)
{
    const int*   tokens = (const int*)  d_in[0];
    const float* emb    = (const float*)d_in[1];
    const float* conv_w = (const float*)d_in[2];
    const float* conv_b = (const float*)d_in[3];
    const float* w1     = (const float*)d_in[4];
    const float* b1     = (const float*)d_in[5];
    const float* w2     = (const float*)d_in[6];
    const float* b2     = (const float*)d_in[7];
    float* out = (float*)d_out;

    const int M = in_sizes[0];   // 32768

    __half *H, *Z, *W1T, *W2T;
    cudaGetSymbolAddress((void**)&H,   g_H);
    cudaGetSymbolAddress((void**)&Z,   g_Z);
    cudaGetSymbolAddress((void**)&W1T, g_w1t);
    cudaGetSymbolAddress((void**)&W2T, g_w2t);

    cudaFuncSetAttribute(mma_gemm_l1,
                         cudaFuncAttributeMaxDynamicSharedMemorySize, L1_SMEM);
    cudaFuncSetAttribute(mma_gemm<true>,
                         cudaFuncAttributeMaxDynamicSharedMemorySize, SMEM_BYTES);
    cudaFuncSetAttribute(mma_gemm<false>,
                         cudaFuncAttributeMaxDynamicSharedMemorySize, SMEM_BYTES);

    const int MB = M / BM;   // 256

    // L1 (fused gather + conv_w cvt + distributed w1/w2 prep):
    //   H = half(relu(emb[tok] @ conv_w^T + conv_b))              [M, 512]
    mma_gemm_l1<<<dim3(512 / BN, MB), 256, L1_SMEM>>>(
        emb, tokens, conv_w, conv_b, H, w1, W1T, w2, W2T);

    // L2: Z = half(relu(H @ W1T^T + b1))                         [M, 1024]
    mma_gemm<true><<<dim3(1024 / BN, MB), 256, SMEM_BYTES>>>(H, W1T, b1, Z, 1024, 512);

    // L3: out = Z @ W2T^T + b2                                   [M, 128]
    mma_gemm<false><<<dim3(128 / BN, MB), 256, SMEM_BYTES>>>(Z, W2T, b2, out, 128, 1024);
}

// round 14
// speedup vs baseline: 1.0100x; 1.0100x over previous
#include <cuda_runtime.h>
#include <cuda_fp16.h>
#include <cstdint>

// ---------------------------------------------------------------------------
// IntentSlotLabellingModel on GB300 (sm_103a), Round 13:
// Recombination of proven-best pieces:
//  * L1 mainloop: R11's (fused emb-gather A producer, fp16 CW via cp.async,
//    DEPTH=3) — fastest measured L1.
//  * Distributed w1/w2 transpose in L1 CTA prologues (R12-proven safe:
//    consumed only by L2, ordered by kernel boundary).
//  * Slim 256-block CW-cvt pre-kernel (CW is consumed by L1 itself).
//  * L2/L3: byte-identical R9 mainloops (122 / 37 us, at the mma.sync floor).
//   M=32768, E=512, C=512, H=1024, L=128.
// ---------------------------------------------------------------------------

#define BM 128
#define BN 128
#define BK 64
#define DEPTH 3
#define SSTR_H 72                       // padded row stride in halves (144 B)
#define A_STH (BM * SSTR_H)             // 9216 halves / stage
#define B_STH (BN * SSTR_H)             // 9216 halves / stage
#define STG_H (A_STH + B_STH)           // 18432 halves / stage
#define SMEM_BYTES (DEPTH * STG_H * 2)  // 110592 B

__device__ __half g_H[32768L * 512];    // post-conv relu (fp16)
__device__ __half g_Z[32768L * 1024];   // post-dec1 relu (fp16)
__device__ __half g_cw[512L * 512];     // conv_w  fp16 [N,K]
__device__ __half g_w1t[1024L * 512];   // dec_w1 -> fp16 [N,K]
__device__ __half g_w2t[128L * 1024];   // dec_w2 -> fp16 [N,K]

__device__ __forceinline__ uint32_t smem_u32(const void* p) {
    uint32_t a;
    asm("{ .reg .u64 t; cvta.to.shared.u64 t, %1; cvt.u32.u64 %0, t; }"
        : "=r"(a) : "l"(p));
    return a;
}
__device__ __forceinline__ void cp_async16(uint32_t dst, const void* src) {
    asm volatile("cp.async.cg.shared.global [%0], [%1], 16;"
                 :: "r"(dst), "l"(src) : "memory");
}
__device__ __forceinline__ void cp_commit() {
    asm volatile("cp.async.commit_group;" ::: "memory");
}
template <int N> __device__ __forceinline__ void cp_wait() {
    asm volatile("cp.async.wait_group %0;" :: "n"(N) : "memory");
}
__device__ __forceinline__ void mma_f16(float* d, const uint32_t* a, const uint32_t* b) {
    asm volatile(
        "mma.sync.aligned.m16n8k16.row.col.f32.f16.f16.f32 "
        "{%0,%1,%2,%3}, {%4,%5,%6,%7}, {%8,%9}, {%0,%1,%2,%3};"
        : "+f"(d[0]), "+f"(d[1]), "+f"(d[2]), "+f"(d[3])
        : "r"(a[0]), "r"(a[1]), "r"(a[2]), "r"(a[3]), "r"(b[0]), "r"(b[1]));
}

// 32x32 transpose tile with fp16 cvt: in [K,N] -> out [N,K]
__device__ __forceinline__ void tile_transpose_cvt(
    const float* __restrict__ in, __half* __restrict__ out,
    int K, int N, int bx, int by, int tid)
{
    __shared__ float t[32][33];
    int n0 = bx * 32, k0 = by * 32;
    int x = tid & 31, y = tid >> 5;
    #pragma unroll
    for (int i = 0; i < 32; i += 8)
        t[y + i][x] = in[(long)(k0 + y + i) * N + n0 + x];
    __syncthreads();
    #pragma unroll
    for (int i = 0; i < 32; i += 8)
        out[(long)(n0 + y + i) * K + k0 + x] = __float2half_rn(t[x][y + i]);
    __syncthreads();
}

// ---------------------------------------------------------------------------
// L1 fused kernel (R11 mainloop): H[128x128] = relu(emb[tok] @ CW^T + bias)
// A: fp32 emb rows via tokens, register-staged LDG.128 + cvt + STS.64,
//    DEPTH=3 ring (loadA 1 stage ahead, stsA into the free buffer).
// B: fp16 CW [N,K] via cp.async ring. 8 warps (2m x 4n), warp tile 64x32.
// Prologue: CTAs 0..639 transpose one 32x32 w1/w2 tile (consumed by L2/L3).
// ---------------------------------------------------------------------------
__global__ void __launch_bounds__(256, 1)
mma_gemm_l1(const float* __restrict__ emb, const int* __restrict__ tokens,
            const __half* __restrict__ B, const float* __restrict__ bias,
            __half* __restrict__ C, int N, int K,
            const float* __restrict__ w1, __half* __restrict__ w1t,
            const float* __restrict__ w2, __half* __restrict__ w2t)
{
    extern __shared__ __half smem[];
    const uint32_t sbase = smem_u32(smem);

    const int tid  = threadIdx.x;
    const int lane = tid & 31;
    const int warp = tid >> 5;
    const int warp_m = (warp >> 2) * 64;     // 0,64
    const int warp_n = (warp & 3) * 32;      // 0,32,64,96
    const int gr = lane >> 2;
    const int gc = lane & 3;

    const int  n0 = blockIdx.x * BN;
    const long m0 = (long)blockIdx.y * BM;

    // ---- distributed w1/w2 prep (uniform per-CTA branch, before mainloop) --
    {
        int bid = blockIdx.y * gridDim.x + blockIdx.x;   // 0..1023
        if (bid < 512) {
            tile_transpose_cvt(w1, w1t, 512, 1024, bid & 31, bid >> 5, tid);
        } else if (bid < 640) {
            int bb = bid - 512;
            tile_transpose_cvt(w2, w2t, 1024, 128, bb & 3, bb >> 2, tid);
        }
    }

    // ---- A producer: 8 float4 LDG per thread per stage (gathered rows) ----
    const int r_base = tid >> 4;             // 0..15
    const int c4     = (tid & 15) * 4;       // float col 0..60
    const float* a_src[8]; int a_soff[8];
    #pragma unroll
    for (int i = 0; i < 8; i++) {
        int r = r_base + i * 16;             // 0..127
        a_src[i]  = emb + (long)tokens[m0 + r] * 512 + c4;
        a_soff[i] = r * SSTR_H + c4;         // halves within A stage
    }
    // ---- B producer: 4 cp16 per thread ----
    const int rb0 = tid >> 3;                // 0..31
    const int c8  = (tid & 7) * 8;
    const __half* b_base = B + (long)(n0 + rb0) * (long)K + c8;
    const uint32_t b_dst0 = sbase + (uint32_t)(A_STH + rb0 * SSTR_H + c8) * 2u;
    const long  bg_step = 32L * K;
    const uint32_t bs_step = 32u * SSTR_H * 2u;

    const int S = K / BK;                    // 8

    auto issueB = [&](int s) {
        const uint32_t so = (uint32_t)((s % DEPTH) * STG_H * 2);
        const int k0 = s * BK;
        #pragma unroll
        for (int i = 0; i < 4; i++)
            cp_async16(b_dst0 + so + i * bs_step, b_base + k0 + i * bg_step);
    };
    float4 ra[8];
    auto loadA = [&](int s) {
        const int k0 = s * BK;
        #pragma unroll
        for (int i = 0; i < 8; i++)
            ra[i] = *reinterpret_cast<const float4*>(a_src[i] + k0);
    };
    auto stsA = [&](int s) {
        __half* As = smem + (s % DEPTH) * STG_H;
        #pragma unroll
        for (int i = 0; i < 8; i++) {
            __half2 h0 = __floats2half2_rn(ra[i].x, ra[i].y);
            __half2 h1 = __floats2half2_rn(ra[i].z, ra[i].w);
            uint2 u;
            u.x = *reinterpret_cast<uint32_t*>(&h0);
            u.y = *reinterpret_cast<uint32_t*>(&h1);
            *reinterpret_cast<uint2*>(&As[a_soff[i]]) = u;
        }
    };

    loadA(0); stsA(0);
    issueB(0); cp_commit();
    issueB(1); cp_commit();

    float acc[4][4][4];
    #pragma unroll
    for (int mt = 0; mt < 4; mt++)
        #pragma unroll
        for (int nt = 0; nt < 4; nt++)
            #pragma unroll
            for (int r = 0; r < 4; r++)
                acc[mt][nt][r] = 0.0f;

    for (int s = 0; s < S; s++) {
        if (s + 1 < S) loadA(s + 1);         // LDG early, hidden by compute
        cp_wait<DEPTH - 2>();
        __syncthreads();                      // stage s ready (A STS + B cp)
        if (s + 2 < S) { issueB(s + 2); cp_commit(); }

        const __half* As = smem + (s % DEPTH) * STG_H;
        const __half* Bs = As + A_STH;

        #pragma unroll
        for (int ks = 0; ks < BK; ks += 16) {
            uint32_t af[4][4], bf[4][2];
            #pragma unroll
            for (int mt = 0; mt < 4; mt++) {
                int r = (warp_m + mt * 16 + gr) * SSTR_H + ks + gc * 2;
                af[mt][0] = *reinterpret_cast<const uint32_t*>(&As[r]);
                af[mt][1] = *reinterpret_cast<const uint32_t*>(&As[r + 8 * SSTR_H]);
                af[mt][2] = *reinterpret_cast<const uint32_t*>(&As[r + 8]);
                af[mt][3] = *reinterpret_cast<const uint32_t*>(&As[r + 8 * SSTR_H + 8]);
            }
            #pragma unroll
            for (int nt = 0; nt < 4; nt++) {
                int r = (warp_n + nt * 8 + gr) * SSTR_H + ks + gc * 2;
                bf[nt][0] = *reinterpret_cast<const uint32_t*>(&Bs[r]);
                bf[nt][1] = *reinterpret_cast<const uint32_t*>(&Bs[r + 8]);
            }
            #pragma unroll
            for (int mt = 0; mt < 4; mt++)
                #pragma unroll
                for (int nt = 0; nt < 4; nt++)
                    mma_f16(acc[mt][nt], af[mt], bf[nt]);
        }

        if (s + 1 < S) stsA(s + 1);          // into free ring buffer
    }

    // ---- epilogue: bias + relu, half2 stores ----
    #pragma unroll
    for (int nt = 0; nt < 4; nt++) {
        int n = n0 + warp_n + nt * 8 + gc * 2;
        float bb0 = bias[n], bb1 = bias[n + 1];
        #pragma unroll
        for (int mt = 0; mt < 4; mt++) {
            long m = m0 + warp_m + mt * 16 + gr;
            __half2 h0 = __floats2half2_rn(fmaxf(acc[mt][nt][0] + bb0, 0.0f),
                                           fmaxf(acc[mt][nt][1] + bb1, 0.0f));
            __half2 h1 = __floats2half2_rn(fmaxf(acc[mt][nt][2] + bb0, 0.0f),
                                           fmaxf(acc[mt][nt][3] + bb1, 0.0f));
            *reinterpret_cast<__half2*>(C + m * (long)N + n)       = h0;
            *reinterpret_cast<__half2*>(C + (m + 8) * (long)N + n) = h1;
        }
    }
}

// ---------------------------------------------------------------------------
// L2/L3 GEMM (R9 proven, byte-identical): C = A @ B^T + bias
// ---------------------------------------------------------------------------
template <bool HALF_OUT>
__global__ void __launch_bounds__(256, 2)
mma_gemm(const __half* __restrict__ A, const __half* __restrict__ B,
         const float* __restrict__ bias, void* __restrict__ Cv,
         int N, int K)
{
    extern __shared__ __half smem[];
    const uint32_t sbase = smem_u32(smem);

    const int tid  = threadIdx.x;
    const int lane = tid & 31;
    const int warp = tid >> 5;
    const int warp_m = (warp >> 2) * 64;
    const int warp_n = (warp & 3) * 32;
    const int gr = lane >> 2;
    const int gc = lane & 3;

    const int  n0 = blockIdx.x * BN;
    const long m0 = (long)blockIdx.y * BM;

    const int r0 = tid >> 3;
    const int c8 = (tid & 7) * 8;
    const __half* a_base = A + (m0 + r0) * (long)K + c8;
    const __half* b_base = B + (long)(n0 + r0) * (long)K + c8;
    const uint32_t a_dst0 = sbase + (uint32_t)(r0 * SSTR_H + c8) * 2u;
    const uint32_t b_dst0 = sbase + (uint32_t)(A_STH + r0 * SSTR_H + c8) * 2u;
    const long  g_step = 32L * K;
    const uint32_t s_step = 32u * SSTR_H * 2u;

    const int S = K / BK;

    auto issue = [&](int s) {
        const uint32_t so = (uint32_t)((s % DEPTH) * STG_H * 2);
        const int k0 = s * BK;
        #pragma unroll
        for (int i = 0; i < 4; i++)
            cp_async16(a_dst0 + so + i * s_step, a_base + k0 + i * g_step);
        #pragma unroll
        for (int i = 0; i < 4; i++)
            cp_async16(b_dst0 + so + i * s_step, b_base + k0 + i * g_step);
    };

    issue(0); cp_commit();
    issue(1); cp_commit();

    float acc[4][4][4];
    #pragma unroll
    for (int mt = 0; mt < 4; mt++)
        #pragma unroll
        for (int nt = 0; nt < 4; nt++)
            #pragma unroll
            for (int r = 0; r < 4; r++)
                acc[mt][nt][r] = 0.0f;

    for (int s = 0; s < S; s++) {
        cp_wait<DEPTH - 2>();
        __syncthreads();
        if (s + 2 < S) issue(s + 2);
        cp_commit();

        const __half* As = smem + (s % DEPTH) * STG_H;
        const __half* Bs = As + A_STH;

        #pragma unroll
        for (int ks = 0; ks < BK; ks += 16) {
            uint32_t af[4][4], bf[4][2];
            #pragma unroll
            for (int mt = 0; mt < 4; mt++) {
                int r = (warp_m + mt * 16 + gr) * SSTR_H + ks + gc * 2;
                af[mt][0] = *reinterpret_cast<const uint32_t*>(&As[r]);
                af[mt][1] = *reinterpret_cast<const uint32_t*>(&As[r + 8 * SSTR_H]);
                af[mt][2] = *reinterpret_cast<const uint32_t*>(&As[r + 8]);
                af[mt][3] = *reinterpret_cast<const uint32_t*>(&As[r + 8 * SSTR_H + 8]);
            }
            #pragma unroll
            for (int nt = 0; nt < 4; nt++) {
                int r = (warp_n + nt * 8 + gr) * SSTR_H + ks + gc * 2;
                bf[nt][0] = *reinterpret_cast<const uint32_t*>(&Bs[r]);
                bf[nt][1] = *reinterpret_cast<const uint32_t*>(&Bs[r + 8]);
            }
            #pragma unroll
            for (int mt = 0; mt < 4; mt++)
                #pragma unroll
                for (int nt = 0; nt < 4; nt++)
                    mma_f16(acc[mt][nt], af[mt], bf[nt]);
        }
    }

    #pragma unroll
    for (int nt = 0; nt < 4; nt++) {
        int n = n0 + warp_n + nt * 8 + gc * 2;
        float bb0 = bias[n], bb1 = bias[n + 1];
        #pragma unroll
        for (int mt = 0; mt < 4; mt++) {
            long m = m0 + warp_m + mt * 16 + gr;
            float x0 = acc[mt][nt][0] + bb0, x1 = acc[mt][nt][1] + bb1;
            float x2 = acc[mt][nt][2] + bb0, x3 = acc[mt][nt][3] + bb1;
            if (HALF_OUT) {
                __half* C = (__half*)Cv;
                __half2 h0 = __floats2half2_rn(fmaxf(x0, 0.0f), fmaxf(x1, 0.0f));
                __half2 h1 = __floats2half2_rn(fmaxf(x2, 0.0f), fmaxf(x3, 0.0f));
                *reinterpret_cast<__half2*>(C + m * (long)N + n)       = h0;
                *reinterpret_cast<__half2*>(C + (m + 8) * (long)N + n) = h1;
            } else {
                float* C = (float*)Cv;
                *reinterpret_cast<float2*>(C + m * (long)N + n)       = make_float2(x0, x1);
                *reinterpret_cast<float2*>(C + (m + 8) * (long)N + n) = make_float2(x2, x3);
            }
        }
    }
}

// ---------------------------------------------------------------------------
// Slim pre-pass: conv_w fp32 -> fp16 (CW is consumed by L1 itself)
// ---------------------------------------------------------------------------
__global__ void cvt_cw(const float* __restrict__ in, __half* __restrict__ out)
{
    long i = ((long)blockIdx.x * blockDim.x + threadIdx.x) * 4;
    const float4 v = *reinterpret_cast<const float4*>(in + i);
    *reinterpret_cast<__half2*>(out + i)     = __floats2half2_rn(v.x, v.y);
    *reinterpret_cast<__half2*>(out + i + 2) = __floats2half2_rn(v.z, v.w);
}

extern "C" void kernel_launch(void* const* d_in, const int* in_sizes, int n_in,
                              void* d_out, int out_size)
{
    const int*   tokens = (const int*)  d_in[0];
    const float* emb    = (const float*)d_in[1];
    const float* conv_w = (const float*)d_in[2];
    const float* conv_b = (const float*)d_in[3];
    const float* w1     = (const float*)d_in[4];
    const float* b1     = (const float*)d_in[5];
    const float* w2     = (const float*)d_in[6];
    const float* b2     = (const float*)d_in[7];
    float* out = (float*)d_out;

    const int M = in_sizes[0];   // 32768

    __half *H, *Z, *CW, *W1T, *W2T;
    cudaGetSymbolAddress((void**)&H,   g_H);
    cudaGetSymbolAddress((void**)&Z,   g_Z);
    cudaGetSymbolAddress((void**)&CW,  g_cw);
    cudaGetSymbolAddress((void**)&W1T, g_w1t);
    cudaGetSymbolAddress((void**)&W2T, g_w2t);

    // CW cvt only (w1/w2 transposes are distributed into L1's CTAs)
    cvt_cw<<<512 * 512 / 4 / 256, 256>>>(conv_w, CW);

    cudaFuncSetAttribute(mma_gemm_l1,
                         cudaFuncAttributeMaxDynamicSharedMemorySize, SMEM_BYTES);
    cudaFuncSetAttribute(mma_gemm<true>,
                         cudaFuncAttributeMaxDynamicSharedMemorySize, SMEM_BYTES);
    cudaFuncSetAttribute(mma_gemm<false>,
                         cudaFuncAttributeMaxDynamicSharedMemorySize, SMEM_BYTES);

    const int MB = M / BM;   // 256

    // L1 (fused gather + distributed w1/w2 prep):
    //   H = half(relu(emb[tok] @ CW^T + conv_b))                  [M, 512]
    mma_gemm_l1<<<dim3(512 / BN, MB), 256, SMEM_BYTES>>>(
        emb, tokens, CW, conv_b, H, 512, 512, w1, W1T, w2, W2T);

    // L2: Z = half(relu(H @ W1T^T + b1))                          [M, 1024]
    mma_gemm<true><<<dim3(1024 / BN, MB), 256, SMEM_BYTES>>>(H, W1T, b1, Z, 1024, 512);

    // L3: out = Z @ W2T^T + b2                                    [M, 128]
    mma_gemm<false><<<dim3(128 / BN, MB), 256, SMEM_BYTES>>>(Z, W2T, b2, out, 128, 1024);
}

// round 15
// speedup vs baseline: 1.0176x; 1.0075x over previous
#include <cuda_runtime.h>
#include <cuda_fp16.h>
#include <cstdint>

// ---------------------------------------------------------------------------
// IntentSlotLabellingModel on GB300 (sm_103a), Round 14:
// R11 base (240.4us, best) + Programmatic Dependent Launch overlap:
//  * prep/L1/L2 call griddepcontrol.launch_dependents after their mainloops;
//  * L1/L2/L3 are launched with ProgrammaticStreamSerialization and do their
//    setup + B-operand (weight) cp.async prefetch BEFORE griddepcontrol.wait,
//    A-operand issues after — B never depends on the predecessor kernel.
// Mainloops byte-identical to R11 (all at the measured mma.sync rate floor).
//   M=32768, E=512, C=512, H=1024, L=128.
// ---------------------------------------------------------------------------

#define BM 128
#define BN 128
#define BK 64
#define DEPTH 3
#define SSTR_H 72                       // padded row stride in halves (144 B)
#define A_STH (BM * SSTR_H)             // 9216 halves / stage
#define B_STH (BN * SSTR_H)             // 9216 halves / stage
#define STG_H (A_STH + B_STH)           // 18432 halves / stage
#define SMEM_BYTES (DEPTH * STG_H * 2)  // 110592 B

__device__ __half g_H[32768L * 512];    // post-conv relu (fp16)
__device__ __half g_Z[32768L * 1024];   // post-dec1 relu (fp16)
__device__ __half g_cw[512L * 512];     // conv_w  fp16 [N,K]
__device__ __half g_w1t[1024L * 512];   // dec_w1 -> fp16 [N,K]
__device__ __half g_w2t[128L * 1024];   // dec_w2 -> fp16 [N,K]

__device__ __forceinline__ uint32_t smem_u32(const void* p) {
    uint32_t a;
    asm("{ .reg .u64 t; cvta.to.shared.u64 t, %1; cvt.u32.u64 %0, t; }"
        : "=r"(a) : "l"(p));
    return a;
}
__device__ __forceinline__ void cp_async16(uint32_t dst, const void* src) {
    asm volatile("cp.async.cg.shared.global [%0], [%1], 16;"
                 :: "r"(dst), "l"(src) : "memory");
}
__device__ __forceinline__ void cp_commit() {
    asm volatile("cp.async.commit_group;" ::: "memory");
}
template <int N> __device__ __forceinline__ void cp_wait() {
    asm volatile("cp.async.wait_group %0;" :: "n"(N) : "memory");
}
__device__ __forceinline__ void pdl_trigger() {
    asm volatile("griddepcontrol.launch_dependents;" ::: "memory");
}
__device__ __forceinline__ void pdl_wait() {
    asm volatile("griddepcontrol.wait;" ::: "memory");
}
__device__ __forceinline__ void mma_f16(float* d, const uint32_t* a, const uint32_t* b) {
    asm volatile(
        "mma.sync.aligned.m16n8k16.row.col.f32.f16.f16.f32 "
        "{%0,%1,%2,%3}, {%4,%5,%6,%7}, {%8,%9}, {%0,%1,%2,%3};"
        : "+f"(d[0]), "+f"(d[1]), "+f"(d[2]), "+f"(d[3])
        : "r"(a[0]), "r"(a[1]), "r"(a[2]), "r"(a[3]), "r"(b[0]), "r"(b[1]));
}

// ---------------------------------------------------------------------------
// Weight prep (R11): w1/w2 transpose + conv_w cvt, 896 blocks.
// ---------------------------------------------------------------------------
__device__ __forceinline__ void tile_transpose_cvt(
    const float* __restrict__ in, __half* __restrict__ out,
    int K, int N, int bx, int by, int tid)
{
    __shared__ float t[32][33];
    int n0 = bx * 32, k0 = by * 32;
    int x = tid & 31, y = tid >> 5;
    #pragma unroll
    for (int i = 0; i < 32; i += 8)
        t[y + i][x] = in[(long)(k0 + y + i) * N + n0 + x];
    __syncthreads();
    #pragma unroll
    for (int i = 0; i < 32; i += 8)
        out[(long)(n0 + y + i) * K + k0 + x] = __float2half_rn(t[x][y + i]);
}

__global__ void prep_weights(const float* __restrict__ w1, __half* __restrict__ w1t,
                             const float* __restrict__ w2, __half* __restrict__ w2t,
                             const float* __restrict__ cw, __half* __restrict__ cwh)
{
    pdl_trigger();                        // let L1 launch + do its pre-wait setup
    const int b = blockIdx.x;
    const int tid = threadIdx.x;
    if (b < 512) {
        tile_transpose_cvt(w1, w1t, 512, 1024, b & 31, b >> 5, tid);
    } else if (b < 640) {
        int bb = b - 512;
        tile_transpose_cvt(w2, w2t, 1024, 128, bb & 3, bb >> 2, tid);
    } else {
        long i = ((long)(b - 640) * 256 + tid) * 4;
        const float4 v = *reinterpret_cast<const float4*>(cw + i);
        *reinterpret_cast<__half2*>(cwh + i)     = __floats2half2_rn(v.x, v.y);
        *reinterpret_cast<__half2*>(cwh + i + 2) = __floats2half2_rn(v.z, v.w);
    }
}

// ---------------------------------------------------------------------------
// L1 fused kernel (R11 mainloop): H[128x128] = relu(emb[tok] @ CW^T + bias)
// A (emb rows, inputs — no dependency) staged BEFORE pdl_wait; B (CW, from
// prep) issued after. Trigger before epilogue lets L2 start early.
// ---------------------------------------------------------------------------
__global__ void __launch_bounds__(256, 1)
mma_gemm_l1(const float* __restrict__ emb, const int* __restrict__ tokens,
            const __half* __restrict__ B, const float* __restrict__ bias,
            __half* __restrict__ C, int N, int K)
{
    extern __shared__ __half smem[];
    const uint32_t sbase = smem_u32(smem);

    const int tid  = threadIdx.x;
    const int lane = tid & 31;
    const int warp = tid >> 5;
    const int warp_m = (warp >> 2) * 64;     // 0,64
    const int warp_n = (warp & 3) * 32;      // 0,32,64,96
    const int gr = lane >> 2;
    const int gc = lane & 3;

    const int  n0 = blockIdx.x * BN;
    const long m0 = (long)blockIdx.y * BM;

    // ---- A producer setup + stage-0 load (inputs only: safe pre-wait) ----
    const int r_base = tid >> 4;             // 0..15
    const int c4     = (tid & 15) * 4;       // float col 0..60
    const float* a_src[8]; int a_soff[8];
    #pragma unroll
    for (int i = 0; i < 8; i++) {
        int r = r_base + i * 16;             // 0..127
        a_src[i]  = emb + (long)tokens[m0 + r] * 512 + c4;
        a_soff[i] = r * SSTR_H + c4;
    }
    // ---- B producer setup ----
    const int rb0 = tid >> 3;                // 0..31
    const int c8  = (tid & 7) * 8;
    const __half* b_base = B + (long)(n0 + rb0) * (long)K + c8;
    const uint32_t b_dst0 = sbase + (uint32_t)(A_STH + rb0 * SSTR_H + c8) * 2u;
    const long  bg_step = 32L * K;
    const uint32_t bs_step = 32u * SSTR_H * 2u;

    const int S = K / BK;                    // 8

    auto issueB = [&](int s) {
        const uint32_t so = (uint32_t)((s % DEPTH) * STG_H * 2);
        const int k0 = s * BK;
        #pragma unroll
        for (int i = 0; i < 4; i++)
            cp_async16(b_dst0 + so + i * bs_step, b_base + k0 + i * bg_step);
    };
    float4 ra[8];
    auto loadA = [&](int s) {
        const int k0 = s * BK;
        #pragma unroll
        for (int i = 0; i < 8; i++)
            ra[i] = *reinterpret_cast<const float4*>(a_src[i] + k0);
    };
    auto stsA = [&](int s) {
        __half* As = smem + (s % DEPTH) * STG_H;
        #pragma unroll
        for (int i = 0; i < 8; i++) {
            __half2 h0 = __floats2half2_rn(ra[i].x, ra[i].y);
            __half2 h1 = __floats2half2_rn(ra[i].z, ra[i].w);
            uint2 u;
            u.x = *reinterpret_cast<uint32_t*>(&h0);
            u.y = *reinterpret_cast<uint32_t*>(&h1);
            *reinterpret_cast<uint2*>(&As[a_soff[i]]) = u;
        }
    };

    loadA(0); stsA(0);                       // pre-wait work (inputs only)
    pdl_wait();                              // CW (from prep) now visible
    issueB(0); cp_commit();
    issueB(1); cp_commit();

    float acc[4][4][4];
    #pragma unroll
    for (int mt = 0; mt < 4; mt++)
        #pragma unroll
        for (int nt = 0; nt < 4; nt++)
            #pragma unroll
            for (int r = 0; r < 4; r++)
                acc[mt][nt][r] = 0.0f;

    for (int s = 0; s < S; s++) {
        if (s + 1 < S) loadA(s + 1);
        cp_wait<DEPTH - 2>();
        __syncthreads();
        if (s + 2 < S) { issueB(s + 2); cp_commit(); }

        const __half* As = smem + (s % DEPTH) * STG_H;
        const __half* Bs = As + A_STH;

        #pragma unroll
        for (int ks = 0; ks < BK; ks += 16) {
            uint32_t af[4][4], bf[4][2];
            #pragma unroll
            for (int mt = 0; mt < 4; mt++) {
                int r = (warp_m + mt * 16 + gr) * SSTR_H + ks + gc * 2;
                af[mt][0] = *reinterpret_cast<const uint32_t*>(&As[r]);
                af[mt][1] = *reinterpret_cast<const uint32_t*>(&As[r + 8 * SSTR_H]);
                af[mt][2] = *reinterpret_cast<const uint32_t*>(&As[r + 8]);
                af[mt][3] = *reinterpret_cast<const uint32_t*>(&As[r + 8 * SSTR_H + 8]);
            }
            #pragma unroll
            for (int nt = 0; nt < 4; nt++) {
                int r = (warp_n + nt * 8 + gr) * SSTR_H + ks + gc * 2;
                bf[nt][0] = *reinterpret_cast<const uint32_t*>(&Bs[r]);
                bf[nt][1] = *reinterpret_cast<const uint32_t*>(&Bs[r + 8]);
            }
            #pragma unroll
            for (int mt = 0; mt < 4; mt++)
                #pragma unroll
                for (int nt = 0; nt < 4; nt++)
                    mma_f16(acc[mt][nt], af[mt], bf[nt]);
        }

        if (s + 1 < S) stsA(s + 1);
    }

    pdl_trigger();                           // L2 may launch during epilogue

    // ---- epilogue: bias + relu, half2 stores ----
    #pragma unroll
    for (int nt = 0; nt < 4; nt++) {
        int n = n0 + warp_n + nt * 8 + gc * 2;
        float bb0 = bias[n], bb1 = bias[n + 1];
        #pragma unroll
        for (int mt = 0; mt < 4; mt++) {
            long m = m0 + warp_m + mt * 16 + gr;
            __half2 h0 = __floats2half2_rn(fmaxf(acc[mt][nt][0] + bb0, 0.0f),
                                           fmaxf(acc[mt][nt][1] + bb1, 0.0f));
            __half2 h1 = __floats2half2_rn(fmaxf(acc[mt][nt][2] + bb0, 0.0f),
                                           fmaxf(acc[mt][nt][3] + bb1, 0.0f));
            *reinterpret_cast<__half2*>(C + m * (long)N + n)       = h0;
            *reinterpret_cast<__half2*>(C + (m + 8) * (long)N + n) = h1;
        }
    }
}

// ---------------------------------------------------------------------------
// L2/L3 GEMM (R9 mainloop): C = A @ B^T + bias.
// B (weights, ready 2+ kernels back) prefetched BEFORE pdl_wait; A after.
// TRIGGER: emit launch_dependents before epilogue (L2 only meaningful).
// ---------------------------------------------------------------------------
template <bool HALF_OUT>
__global__ void __launch_bounds__(256, 2)
mma_gemm(const __half* __restrict__ A, const __half* __restrict__ B,
         const float* __restrict__ bias, void* __restrict__ Cv,
         int N, int K)
{
    extern __shared__ __half smem[];
    const uint32_t sbase = smem_u32(smem);

    const int tid  = threadIdx.x;
    const int lane = tid & 31;
    const int warp = tid >> 5;
    const int warp_m = (warp >> 2) * 64;
    const int warp_n = (warp & 3) * 32;
    const int gr = lane >> 2;
    const int gc = lane & 3;

    const int  n0 = blockIdx.x * BN;
    const long m0 = (long)blockIdx.y * BM;

    const int r0 = tid >> 3;
    const int c8 = (tid & 7) * 8;
    const __half* a_base = A + (m0 + r0) * (long)K + c8;
    const __half* b_base = B + (long)(n0 + r0) * (long)K + c8;
    const uint32_t a_dst0 = sbase + (uint32_t)(r0 * SSTR_H + c8) * 2u;
    const uint32_t b_dst0 = sbase + (uint32_t)(A_STH + r0 * SSTR_H + c8) * 2u;
    const long  g_step = 32L * K;
    const uint32_t s_step = 32u * SSTR_H * 2u;

    const int S = K / BK;

    auto issueA = [&](int s) {
        const uint32_t so = (uint32_t)((s % DEPTH) * STG_H * 2);
        const int k0 = s * BK;
        #pragma unroll
        for (int i = 0; i < 4; i++)
            cp_async16(a_dst0 + so + i * s_step, a_base + k0 + i * g_step);
    };
    auto issueB = [&](int s) {
        const uint32_t so = (uint32_t)((s % DEPTH) * STG_H * 2);
        const int k0 = s * BK;
        #pragma unroll
        for (int i = 0; i < 4; i++)
            cp_async16(b_dst0 + so + i * s_step, b_base + k0 + i * g_step);
    };

    // prefetch weights while predecessor still runs
    issueB(0); issueB(1);
    pdl_wait();                              // A (predecessor output) visible
    issueA(0); cp_commit();                  // group0 = B0,B1,A0
    issueA(1); cp_commit();                  // group1 = A1

    float acc[4][4][4];
    #pragma unroll
    for (int mt = 0; mt < 4; mt++)
        #pragma unroll
        for (int nt = 0; nt < 4; nt++)
            #pragma unroll
            for (int r = 0; r < 4; r++)
                acc[mt][nt][r] = 0.0f;

    for (int s = 0; s < S; s++) {
        cp_wait<DEPTH - 2>();
        __syncthreads();
        if (s + 2 < S) { issueA(s + 2); issueB(s + 2); }
        cp_commit();

        const __half* As = smem + (s % DEPTH) * STG_H;
        const __half* Bs = As + A_STH;

        #pragma unroll
        for (int ks = 0; ks < BK; ks += 16) {
            uint32_t af[4][4], bf[4][2];
            #pragma unroll
            for (int mt = 0; mt < 4; mt++) {
                int r = (warp_m + mt * 16 + gr) * SSTR_H + ks + gc * 2;
                af[mt][0] = *reinterpret_cast<const uint32_t*>(&As[r]);
                af[mt][1] = *reinterpret_cast<const uint32_t*>(&As[r + 8 * SSTR_H]);
                af[mt][2] = *reinterpret_cast<const uint32_t*>(&As[r + 8]);
                af[mt][3] = *reinterpret_cast<const uint32_t*>(&As[r + 8 * SSTR_H + 8]);
            }
            #pragma unroll
            for (int nt = 0; nt < 4; nt++) {
                int r = (warp_n + nt * 8 + gr) * SSTR_H + ks + gc * 2;
                bf[nt][0] = *reinterpret_cast<const uint32_t*>(&Bs[r]);
                bf[nt][1] = *reinterpret_cast<const uint32_t*>(&Bs[r + 8]);
            }
            #pragma unroll
            for (int mt = 0; mt < 4; mt++)
                #pragma unroll
                for (int nt = 0; nt < 4; nt++)
                    mma_f16(acc[mt][nt], af[mt], bf[nt]);
        }
    }

    pdl_trigger();                           // successor may launch now

    #pragma unroll
    for (int nt = 0; nt < 4; nt++) {
        int n = n0 + warp_n + nt * 8 + gc * 2;
        float bb0 = bias[n], bb1 = bias[n + 1];
        #pragma unroll
        for (int mt = 0; mt < 4; mt++) {
            long m = m0 + warp_m + mt * 16 + gr;
            float x0 = acc[mt][nt][0] + bb0, x1 = acc[mt][nt][1] + bb1;
            float x2 = acc[mt][nt][2] + bb0, x3 = acc[mt][nt][3] + bb1;
            if (HALF_OUT) {
                __half* C = (__half*)Cv;
                __half2 h0 = __floats2half2_rn(fmaxf(x0, 0.0f), fmaxf(x1, 0.0f));
                __half2 h1 = __floats2half2_rn(fmaxf(x2, 0.0f), fmaxf(x3, 0.0f));
                *reinterpret_cast<__half2*>(C + m * (long)N + n)       = h0;
                *reinterpret_cast<__half2*>(C + (m + 8) * (long)N + n) = h1;
            } else {
                float* C = (float*)Cv;
                *reinterpret_cast<float2*>(C + m * (long)N + n)       = make_float2(x0, x1);
                *reinterpret_cast<float2*>(C + (m + 8) * (long)N + n) = make_float2(x2, x3);
            }
        }
    }
}

extern "C" void kernel_launch(void* const* d_in, const int* in_sizes, int n_in,
                              void* d_out, int out_size)
{
    const int*   tokens = (const int*)  d_in[0];
    const float* emb    = (const float*)d_in[1];
    const float* conv_w = (const float*)d_in[2];
    const float* conv_b = (const float*)d_in[3];
    const float* w1     = (const float*)d_in[4];
    const float* b1     = (const float*)d_in[5];
    const float* w2     = (const float*)d_in[6];
    const float* b2     = (const float*)d_in[7];
    float* out = (float*)d_out;

    const int M = in_sizes[0];   // 32768

    __half *H, *Z, *CW, *W1T, *W2T;
    cudaGetSymbolAddress((void**)&H,   g_H);
    cudaGetSymbolAddress((void**)&Z,   g_Z);
    cudaGetSymbolAddress((void**)&CW,  g_cw);
    cudaGetSymbolAddress((void**)&W1T, g_w1t);
    cudaGetSymbolAddress((void**)&W2T, g_w2t);

    cudaFuncSetAttribute(mma_gemm_l1,
                         cudaFuncAttributeMaxDynamicSharedMemorySize, SMEM_BYTES);
    cudaFuncSetAttribute(mma_gemm<true>,
                         cudaFuncAttributeMaxDynamicSharedMemorySize, SMEM_BYTES);
    cudaFuncSetAttribute(mma_gemm<false>,
                         cudaFuncAttributeMaxDynamicSharedMemorySize, SMEM_BYTES);

    const int MB = M / BM;   // 256

    // prep: w1/w2 transpose + CW cvt (triggers dependents immediately)
    prep_weights<<<896, 256>>>(w1, W1T, w2, W2T, conv_w, CW);

    cudaLaunchAttribute attrs[1];
    attrs[0].id = cudaLaunchAttributeProgrammaticStreamSerialization;
    attrs[0].val.programmaticStreamSerializationAllowed = 1;

    // L1: H = half(relu(emb[tok] @ CW^T + conv_b))        [M, 512]
    {
        cudaLaunchConfig_t cfg = {};
        cfg.gridDim = dim3(512 / BN, MB);
        cfg.blockDim = dim3(256);
        cfg.dynamicSmemBytes = SMEM_BYTES;
        cfg.attrs = attrs; cfg.numAttrs = 1;
        cudaLaunchKernelEx(&cfg, mma_gemm_l1,
                           emb, tokens, (const __half*)CW, conv_b, H, 512, 512);
    }
    // L2: Z = half(relu(H @ W1T^T + b1))                  [M, 1024]
    {
        cudaLaunchConfig_t cfg = {};
        cfg.gridDim = dim3(1024 / BN, MB);
        cfg.blockDim = dim3(256);
        cfg.dynamicSmemBytes = SMEM_BYTES;
        cfg.attrs = attrs; cfg.numAttrs = 1;
        cudaLaunchKernelEx(&cfg, mma_gemm<true>,
                           (const __half*)H, (const __half*)W1T, b1, (void*)Z,
                           1024, 512);
    }
    // L3: out = Z @ W2T^T + b2                            [M, 128]
    {
        cudaLaunchConfig_t cfg = {};
        cfg.gridDim = dim3(128 / BN, MB);
        cfg.blockDim = dim3(256);
        cfg.dynamicSmemBytes = SMEM_BYTES;
        cfg.attrs = attrs; cfg.numAttrs = 1;
        cudaLaunchKernelEx(&cfg, mma_gemm<false>,
                           (const __half*)Z, (const __half*)W2T, b2, (void*)out,
                           128, 1024);
    }
}

// round 16
// speedup vs baseline: 1.0546x; 1.0364x over previous
#include <cuda_runtime.h>
#include <cuda_fp16.h>
#include <cstdint>

// ---------------------------------------------------------------------------
// IntentSlotLabellingModel on GB300 (sm_103a), Round 15:
// R14 base (= R11 perf, 240.4us) + occ-2 fused-gather L1:
//  * L1 staging halved (ra[4], two batches threaded through the compute) so
//    regs fit the 128/thread cap at 2 CTAs/SM — L1 is producer-latency-bound
//    (not rate-floor-bound), so doubling resident warps should close part of
//    its 78-vs-61us gap. L2/L3/prep byte-identical (at the mma.sync floor).
//   M=32768, E=512, C=512, H=1024, L=128.
// ---------------------------------------------------------------------------

#define BM 128
#define BN 128
#define BK 64
#define DEPTH 3
#define SSTR_H 72                       // padded row stride in halves (144 B)
#define A_STH (BM * SSTR_H)             // 9216 halves / stage
#define B_STH (BN * SSTR_H)             // 9216 halves / stage
#define STG_H (A_STH + B_STH)           // 18432 halves / stage
#define SMEM_BYTES (DEPTH * STG_H * 2)  // 110592 B -> 2 CTAs/SM

__device__ __half g_H[32768L * 512];    // post-conv relu (fp16)
__device__ __half g_Z[32768L * 1024];   // post-dec1 relu (fp16)
__device__ __half g_cw[512L * 512];     // conv_w  fp16 [N,K]
__device__ __half g_w1t[1024L * 512];   // dec_w1 -> fp16 [N,K]
__device__ __half g_w2t[128L * 1024];   // dec_w2 -> fp16 [N,K]

__device__ __forceinline__ uint32_t smem_u32(const void* p) {
    uint32_t a;
    asm("{ .reg .u64 t; cvta.to.shared.u64 t, %1; cvt.u32.u64 %0, t; }"
        : "=r"(a) : "l"(p));
    return a;
}
__device__ __forceinline__ void cp_async16(uint32_t dst, const void* src) {
    asm volatile("cp.async.cg.shared.global [%0], [%1], 16;"
                 :: "r"(dst), "l"(src) : "memory");
}
__device__ __forceinline__ void cp_commit() {
    asm volatile("cp.async.commit_group;" ::: "memory");
}
template <int N> __device__ __forceinline__ void cp_wait() {
    asm volatile("cp.async.wait_group %0;" :: "n"(N) : "memory");
}
__device__ __forceinline__ void pdl_trigger() {
    asm volatile("griddepcontrol.launch_dependents;" ::: "memory");
}
__device__ __forceinline__ void pdl_wait() {
    asm volatile("griddepcontrol.wait;" ::: "memory");
}
__device__ __forceinline__ void mma_f16(float* d, const uint32_t* a, const uint32_t* b) {
    asm volatile(
        "mma.sync.aligned.m16n8k16.row.col.f32.f16.f16.f32 "
        "{%0,%1,%2,%3}, {%4,%5,%6,%7}, {%8,%9}, {%0,%1,%2,%3};"
        : "+f"(d[0]), "+f"(d[1]), "+f"(d[2]), "+f"(d[3])
        : "r"(a[0]), "r"(a[1]), "r"(a[2]), "r"(a[3]), "r"(b[0]), "r"(b[1]));
}

// ---------------------------------------------------------------------------
// Weight prep: w1/w2 transpose + conv_w cvt, 896 blocks.
// ---------------------------------------------------------------------------
__device__ __forceinline__ void tile_transpose_cvt(
    const float* __restrict__ in, __half* __restrict__ out,
    int K, int N, int bx, int by, int tid)
{
    __shared__ float t[32][33];
    int n0 = bx * 32, k0 = by * 32;
    int x = tid & 31, y = tid >> 5;
    #pragma unroll
    for (int i = 0; i < 32; i += 8)
        t[y + i][x] = in[(long)(k0 + y + i) * N + n0 + x];
    __syncthreads();
    #pragma unroll
    for (int i = 0; i < 32; i += 8)
        out[(long)(n0 + y + i) * K + k0 + x] = __float2half_rn(t[x][y + i]);
}

__global__ void prep_weights(const float* __restrict__ w1, __half* __restrict__ w1t,
                             const float* __restrict__ w2, __half* __restrict__ w2t,
                             const float* __restrict__ cw, __half* __restrict__ cwh)
{
    pdl_trigger();
    const int b = blockIdx.x;
    const int tid = threadIdx.x;
    if (b < 512) {
        tile_transpose_cvt(w1, w1t, 512, 1024, b & 31, b >> 5, tid);
    } else if (b < 640) {
        int bb = b - 512;
        tile_transpose_cvt(w2, w2t, 1024, 128, bb & 3, bb >> 2, tid);
    } else {
        long i = ((long)(b - 640) * 256 + tid) * 4;
        const float4 v = *reinterpret_cast<const float4*>(cw + i);
        *reinterpret_cast<__half2*>(cwh + i)     = __floats2half2_rn(v.x, v.y);
        *reinterpret_cast<__half2*>(cwh + i + 2) = __floats2half2_rn(v.z, v.w);
    }
}

// ---------------------------------------------------------------------------
// L1 fused kernel, occ 2: H[128x128] = relu(emb[tok] @ CW^T + bias)
// A: fp32 emb rows, register-staged in TWO 4-float4 batches per stage
//    (batch0 LDG pre-barrier; batch0 STS + batch1 LDG at ks==16; batch1 STS
//    post-compute) -> ra[4] keeps regs <= 128 at 2 CTAs/SM.
// B: fp16 CW via cp.async DEPTH=3 ring. 8 warps (2m x 4n), warp tile 64x32.
// ---------------------------------------------------------------------------
__global__ void __launch_bounds__(256, 2)
mma_gemm_l1(const float* __restrict__ emb, const int* __restrict__ tokens,
            const __half* __restrict__ B, const float* __restrict__ bias,
            __half* __restrict__ C, int N, int K)
{
    extern __shared__ __half smem[];
    const uint32_t sbase = smem_u32(smem);

    const int tid  = threadIdx.x;
    const int lane = tid & 31;
    const int warp = tid >> 5;
    const int warp_m = (warp >> 2) * 64;     // 0,64
    const int warp_n = (warp & 3) * 32;      // 0,32,64,96
    const int gr = lane >> 2;
    const int gc = lane & 3;

    const int  n0 = blockIdx.x * BN;
    const long m0 = (long)blockIdx.y * BM;

    // ---- A producer: rows r_base + i*16 (i<8), split into batches of 4 ----
    const int r_base = tid >> 4;             // 0..15
    const int c4     = (tid & 15) * 4;       // float col 0..60
    const float* a_src[8]; int a_soff[8];
    #pragma unroll
    for (int i = 0; i < 8; i++) {
        int r = r_base + i * 16;             // 0..127
        a_src[i]  = emb + (long)tokens[m0 + r] * 512 + c4;
        a_soff[i] = r * SSTR_H + c4;
    }
    // ---- B producer: 4 cp16 per thread ----
    const int rb0 = tid >> 3;                // 0..31
    const int c8  = (tid & 7) * 8;
    const __half* b_base = B + (long)(n0 + rb0) * (long)K + c8;
    const uint32_t b_dst0 = sbase + (uint32_t)(A_STH + rb0 * SSTR_H + c8) * 2u;
    const long  bg_step = 32L * K;
    const uint32_t bs_step = 32u * SSTR_H * 2u;

    const int S = K / BK;                    // 8

    auto issueB = [&](int s) {
        const uint32_t so = (uint32_t)((s % DEPTH) * STG_H * 2);
        const int k0 = s * BK;
        #pragma unroll
        for (int i = 0; i < 4; i++)
            cp_async16(b_dst0 + so + i * bs_step, b_base + k0 + i * bg_step);
    };

    float4 ra[4];                            // 16 regs staging (half batch)
    auto loadA4 = [&](int s, int h) {
        const int k0 = s * BK;
        #pragma unroll
        for (int i = 0; i < 4; i++)
            ra[i] = *reinterpret_cast<const float4*>(a_src[h * 4 + i] + k0);
    };
    auto stsA4 = [&](int s, int h) {
        __half* As = smem + (s % DEPTH) * STG_H;
        #pragma unroll
        for (int i = 0; i < 4; i++) {
            __half2 h0 = __floats2half2_rn(ra[i].x, ra[i].y);
            __half2 h1 = __floats2half2_rn(ra[i].z, ra[i].w);
            uint2 u;
            u.x = *reinterpret_cast<uint32_t*>(&h0);
            u.y = *reinterpret_cast<uint32_t*>(&h1);
            *reinterpret_cast<uint2*>(&As[a_soff[h * 4 + i]]) = u;
        }
    };

    loadA4(0, 0); stsA4(0, 0);
    loadA4(0, 1); stsA4(0, 1);               // stage 0 fully staged
    pdl_wait();                              // CW (from prep) now visible
    issueB(0); cp_commit();
    issueB(1); cp_commit();

    float acc[4][4][4];
    #pragma unroll
    for (int mt = 0; mt < 4; mt++)
        #pragma unroll
        for (int nt = 0; nt < 4; nt++)
            #pragma unroll
            for (int r = 0; r < 4; r++)
                acc[mt][nt][r] = 0.0f;

    for (int s = 0; s < S; s++) {
        if (s + 1 < S) loadA4(s + 1, 0);     // batch0 LDG early
        cp_wait<DEPTH - 2>();
        __syncthreads();                      // stage s ready
        if (s + 2 < S) { issueB(s + 2); cp_commit(); }

        const __half* As = smem + (s % DEPTH) * STG_H;
        const __half* Bs = As + A_STH;

        #pragma unroll
        for (int ks = 0; ks < BK; ks += 16) {
            uint32_t af[4][4], bf[4][2];
            #pragma unroll
            for (int mt = 0; mt < 4; mt++) {
                int r = (warp_m + mt * 16 + gr) * SSTR_H + ks + gc * 2;
                af[mt][0] = *reinterpret_cast<const uint32_t*>(&As[r]);
                af[mt][1] = *reinterpret_cast<const uint32_t*>(&As[r + 8 * SSTR_H]);
                af[mt][2] = *reinterpret_cast<const uint32_t*>(&As[r + 8]);
                af[mt][3] = *reinterpret_cast<const uint32_t*>(&As[r + 8 * SSTR_H + 8]);
            }
            #pragma unroll
            for (int nt = 0; nt < 4; nt++) {
                int r = (warp_n + nt * 8 + gr) * SSTR_H + ks + gc * 2;
                bf[nt][0] = *reinterpret_cast<const uint32_t*>(&Bs[r]);
                bf[nt][1] = *reinterpret_cast<const uint32_t*>(&Bs[r + 8]);
            }
            #pragma unroll
            for (int mt = 0; mt < 4; mt++)
                #pragma unroll
                for (int nt = 0; nt < 4; nt++)
                    mma_f16(acc[mt][nt], af[mt], bf[nt]);

            // mid-stage: flush batch0, start batch1 (compile-time branch)
            if (ks == 16 && s + 1 < S) {
                stsA4(s + 1, 0);
                loadA4(s + 1, 1);
            }
        }

        if (s + 1 < S) stsA4(s + 1, 1);      // flush batch1
    }

    pdl_trigger();

    // ---- epilogue: bias + relu, half2 stores ----
    #pragma unroll
    for (int nt = 0; nt < 4; nt++) {
        int n = n0 + warp_n + nt * 8 + gc * 2;
        float bb0 = bias[n], bb1 = bias[n + 1];
        #pragma unroll
        for (int mt = 0; mt < 4; mt++) {
            long m = m0 + warp_m + mt * 16 + gr;
            __half2 h0 = __floats2half2_rn(fmaxf(acc[mt][nt][0] + bb0, 0.0f),
                                           fmaxf(acc[mt][nt][1] + bb1, 0.0f));
            __half2 h1 = __floats2half2_rn(fmaxf(acc[mt][nt][2] + bb0, 0.0f),
                                           fmaxf(acc[mt][nt][3] + bb1, 0.0f));
            *reinterpret_cast<__half2*>(C + m * (long)N + n)       = h0;
            *reinterpret_cast<__half2*>(C + (m + 8) * (long)N + n) = h1;
        }
    }
}

// ---------------------------------------------------------------------------
// L2/L3 GEMM (proven mainloop, PDL-wrapped): C = A @ B^T + bias
// ---------------------------------------------------------------------------
template <bool HALF_OUT>
__global__ void __launch_bounds__(256, 2)
mma_gemm(const __half* __restrict__ A, const __half* __restrict__ B,
         const float* __restrict__ bias, void* __restrict__ Cv,
         int N, int K)
{
    extern __shared__ __half smem[];
    const uint32_t sbase = smem_u32(smem);

    const int tid  = threadIdx.x;
    const int lane = tid & 31;
    const int warp = tid >> 5;
    const int warp_m = (warp >> 2) * 64;
    const int warp_n = (warp & 3) * 32;
    const int gr = lane >> 2;
    const int gc = lane & 3;

    const int  n0 = blockIdx.x * BN;
    const long m0 = (long)blockIdx.y * BM;

    const int r0 = tid >> 3;
    const int c8 = (tid & 7) * 8;
    const __half* a_base = A + (m0 + r0) * (long)K + c8;
    const __half* b_base = B + (long)(n0 + r0) * (long)K + c8;
    const uint32_t a_dst0 = sbase + (uint32_t)(r0 * SSTR_H + c8) * 2u;
    const uint32_t b_dst0 = sbase + (uint32_t)(A_STH + r0 * SSTR_H + c8) * 2u;
    const long  g_step = 32L * K;
    const uint32_t s_step = 32u * SSTR_H * 2u;

    const int S = K / BK;

    auto issueA = [&](int s) {
        const uint32_t so = (uint32_t)((s % DEPTH) * STG_H * 2);
        const int k0 = s * BK;
        #pragma unroll
        for (int i = 0; i < 4; i++)
            cp_async16(a_dst0 + so + i * s_step, a_base + k0 + i * g_step);
    };
    auto issueB = [&](int s) {
        const uint32_t so = (uint32_t)((s % DEPTH) * STG_H * 2);
        const int k0 = s * BK;
        #pragma unroll
        for (int i = 0; i < 4; i++)
            cp_async16(b_dst0 + so + i * s_step, b_base + k0 + i * g_step);
    };

    issueB(0); issueB(1);                    // weights: no dependency
    pdl_wait();
    issueA(0); cp_commit();
    issueA(1); cp_commit();

    float acc[4][4][4];
    #pragma unroll
    for (int mt = 0; mt < 4; mt++)
        #pragma unroll
        for (int nt = 0; nt < 4; nt++)
            #pragma unroll
            for (int r = 0; r < 4; r++)
                acc[mt][nt][r] = 0.0f;

    for (int s = 0; s < S; s++) {
        cp_wait<DEPTH - 2>();
        __syncthreads();
        if (s + 2 < S) { issueA(s + 2); issueB(s + 2); }
        cp_commit();

        const __half* As = smem + (s % DEPTH) * STG_H;
        const __half* Bs = As + A_STH;

        #pragma unroll
        for (int ks = 0; ks < BK; ks += 16) {
            uint32_t af[4][4], bf[4][2];
            #pragma unroll
            for (int mt = 0; mt < 4; mt++) {
                int r = (warp_m + mt * 16 + gr) * SSTR_H + ks + gc * 2;
                af[mt][0] = *reinterpret_cast<const uint32_t*>(&As[r]);
                af[mt][1] = *reinterpret_cast<const uint32_t*>(&As[r + 8 * SSTR_H]);
                af[mt][2] = *reinterpret_cast<const uint32_t*>(&As[r + 8]);
                af[mt][3] = *reinterpret_cast<const uint32_t*>(&As[r + 8 * SSTR_H + 8]);
            }
            #pragma unroll
            for (int nt = 0; nt < 4; nt++) {
                int r = (warp_n + nt * 8 + gr) * SSTR_H + ks + gc * 2;
                bf[nt][0] = *reinterpret_cast<const uint32_t*>(&Bs[r]);
                bf[nt][1] = *reinterpret_cast<const uint32_t*>(&Bs[r + 8]);
            }
            #pragma unroll
            for (int mt = 0; mt < 4; mt++)
                #pragma unroll
                for (int nt = 0; nt < 4; nt++)
                    mma_f16(acc[mt][nt], af[mt], bf[nt]);
        }
    }

    pdl_trigger();

    #pragma unroll
    for (int nt = 0; nt < 4; nt++) {
        int n = n0 + warp_n + nt * 8 + gc * 2;
        float bb0 = bias[n], bb1 = bias[n + 1];
        #pragma unroll
        for (int mt = 0; mt < 4; mt++) {
            long m = m0 + warp_m + mt * 16 + gr;
            float x0 = acc[mt][nt][0] + bb0, x1 = acc[mt][nt][1] + bb1;
            float x2 = acc[mt][nt][2] + bb0, x3 = acc[mt][nt][3] + bb1;
            if (HALF_OUT) {
                __half* C = (__half*)Cv;
                __half2 h0 = __floats2half2_rn(fmaxf(x0, 0.0f), fmaxf(x1, 0.0f));
                __half2 h1 = __floats2half2_rn(fmaxf(x2, 0.0f), fmaxf(x3, 0.0f));
                *reinterpret_cast<__half2*>(C + m * (long)N + n)       = h0;
                *reinterpret_cast<__half2*>(C + (m + 8) * (long)N + n) = h1;
            } else {
                float* C = (float*)Cv;
                *reinterpret_cast<float2*>(C + m * (long)N + n)       = make_float2(x0, x1);
                *reinterpret_cast<float2*>(C + (m + 8) * (long)N + n) = make_float2(x2, x3);
            }
        }
    }
}

extern "C" void kernel_launch(void* const* d_in, const int* in_sizes, int n_in,
                              void* d_out, int out_size)
{
    const int*   tokens = (const int*)  d_in[0];
    const float* emb    = (const float*)d_in[1];
    const float* conv_w = (const float*)d_in[2];
    const float* conv_b = (const float*)d_in[3];
    const float* w1     = (const float*)d_in[4];
    const float* b1     = (const float*)d_in[5];
    const float* w2     = (const float*)d_in[6];
    const float* b2     = (const float*)d_in[7];
    float* out = (float*)d_out;

    const int M = in_sizes[0];   // 32768

    __half *H, *Z, *CW, *W1T, *W2T;
    cudaGetSymbolAddress((void**)&H,   g_H);
    cudaGetSymbolAddress((void**)&Z,   g_Z);
    cudaGetSymbolAddress((void**)&CW,  g_cw);
    cudaGetSymbolAddress((void**)&W1T, g_w1t);
    cudaGetSymbolAddress((void**)&W2T, g_w2t);

    cudaFuncSetAttribute(mma_gemm_l1,
                         cudaFuncAttributeMaxDynamicSharedMemorySize, SMEM_BYTES);
    cudaFuncSetAttribute(mma_gemm<true>,
                         cudaFuncAttributeMaxDynamicSharedMemorySize, SMEM_BYTES);
    cudaFuncSetAttribute(mma_gemm<false>,
                         cudaFuncAttributeMaxDynamicSharedMemorySize, SMEM_BYTES);

    const int MB = M / BM;   // 256

    prep_weights<<<896, 256>>>(w1, W1T, w2, W2T, conv_w, CW);

    cudaLaunchAttribute attrs[1];
    attrs[0].id = cudaLaunchAttributeProgrammaticStreamSerialization;
    attrs[0].val.programmaticStreamSerializationAllowed = 1;

    // L1: H = half(relu(emb[tok] @ CW^T + conv_b))        [M, 512]
    {
        cudaLaunchConfig_t cfg = {};
        cfg.gridDim = dim3(512 / BN, MB);
        cfg.blockDim = dim3(256);
        cfg.dynamicSmemBytes = SMEM_BYTES;
        cfg.attrs = attrs; cfg.numAttrs = 1;
        cudaLaunchKernelEx(&cfg, mma_gemm_l1,
                           emb, tokens, (const __half*)CW, conv_b, H, 512, 512);
    }
    // L2: Z = half(relu(H @ W1T^T + b1))                  [M, 1024]
    {
        cudaLaunchConfig_t cfg = {};
        cfg.gridDim = dim3(1024 / BN, MB);
        cfg.blockDim = dim3(256);
        cfg.dynamicSmemBytes = SMEM_BYTES;
        cfg.attrs = attrs; cfg.numAttrs = 1;
        cudaLaunchKernelEx(&cfg, mma_gemm<true>,
                           (const __half*)H, (const __half*)W1T, b1, (void*)Z,
                           1024, 512);
    }
    // L3: out = Z @ W2T^T + b2                            [M, 128]
    {
        cudaLaunchConfig_t cfg = {};
        cfg.gridDim = dim3(128 / BN, MB);
        cfg.blockDim = dim3(256);
        cfg.dynamicSmemBytes = SMEM_BYTES;
        cfg.attrs = attrs; cfg.numAttrs = 1;
        cudaLaunchKernelEx(&cfg, mma_gemm<false>,
                           (const __half*)Z, (const __half*)W2T, b2, (void*)out,
                           128, 1024);
    }
}